// round 1
// baseline (speedup 1.0000x reference)
#include <cuda_runtime.h>

#define NN   50000
#define EE   800000
#define ETOT (EE + NN)
#define HID  128

// ---------------- device scratch (no allocations allowed) ----------------
__device__ float d_h1[NN * HID];   // x @ W1
__device__ float d_t1[NN * HID];   // relu(layer1 out)
__device__ float d_h2[NN * HID];   // t1 @ W2
__device__ float d_t2[NN * HID];   // layer2 out
__device__ float d_al[NN];
__device__ float d_ar[NN];
__device__ float d_scr[ETOT];      // per-edge alpha scratch
__device__ int   d_src[ETOT];      // CSR src list (sorted by dst)
__device__ int   d_rowptr[NN + 1];
__device__ int   d_deg[NN];
__device__ int   d_fill[NN];
__device__ int   d_bsums[64];
__device__ float d_p[NN * 8];      // per-node [p_src(4), p_dst(4)]

// ---------------- CSR build ----------------
__global__ void k_init() {
    int i = blockIdx.x * blockDim.x + threadIdx.x;
    if (i < NN) { d_deg[i] = 1; d_fill[i] = 0; }   // deg starts at 1 (self-loop)
}

__global__ void k_hist(const int* __restrict__ ei) {
    int e = blockIdx.x * blockDim.x + threadIdx.x;
    if (e < EE) atomicAdd(&d_deg[ei[EE + e]], 1);
}

__global__ void k_scan1() {
    __shared__ int sh[1024];
    int tid = threadIdx.x;
    int i = blockIdx.x * 1024 + tid;
    int v = (i < NN) ? d_deg[i] : 0;
    sh[tid] = v;
    __syncthreads();
    #pragma unroll
    for (int off = 1; off < 1024; off <<= 1) {
        int t = (tid >= off) ? sh[tid - off] : 0;
        __syncthreads();
        sh[tid] += t;
        __syncthreads();
    }
    if (i < NN) d_rowptr[i] = sh[tid] - v;             // exclusive within block
    if (tid == 1023) d_bsums[blockIdx.x] = sh[1023];   // block total
}

__global__ void k_scan2(int nb) {
    if (threadIdx.x == 0 && blockIdx.x == 0) {
        int run = 0;
        for (int b = 0; b < nb; b++) { int t = d_bsums[b]; d_bsums[b] = run; run += t; }
        d_rowptr[NN] = run;   // == ETOT
    }
}

__global__ void k_scan3() {
    int i = blockIdx.x * 1024 + threadIdx.x;
    if (i < NN) d_rowptr[i] += d_bsums[blockIdx.x];
}

__global__ void k_scatter(const int* __restrict__ ei) {
    int t = blockIdx.x * blockDim.x + threadIdx.x;
    if (t < EE) {
        int c = ei[EE + t];
        int pos = d_rowptr[c] + atomicAdd(&d_fill[c], 1);
        d_src[pos] = ei[t];
    } else if (t < ETOT) {
        int n = t - EE;
        int pos = d_rowptr[n] + atomicAdd(&d_fill[n], 1);
        d_src[pos] = n;
    }
}

// ---------------- GEMM: C[M,128] = A[M,128] @ B[128,128], fp32 ----------------
// block tile 128x128, thread tile 8x8, 256 threads
__global__ void __launch_bounds__(256) k_gemm(const float* __restrict__ Aext,
                                              const float* __restrict__ B,
                                              int selA, int selC) {
    const float* A = selA ? d_t1 : Aext;
    float* C = selC ? d_h2 : d_h1;

    __shared__ float As[16][132];   // [k][m], padded
    __shared__ float Bs[16][128];   // [k][n]

    int tid = threadIdx.x;
    int tr = tid >> 4, tc = tid & 15;
    int mBase = blockIdx.x * 128;

    float acc[8][8];
    #pragma unroll
    for (int i = 0; i < 8; i++)
        #pragma unroll
        for (int j = 0; j < 8; j++) acc[i][j] = 0.f;

    for (int kc = 0; kc < 128; kc += 16) {
        #pragma unroll
        for (int l = 0; l < 2; l++) {
            int f = tid + l * 256;
            // A tile: 128 rows x 16 ks = 512 float4
            int r = f >> 2, cg = (f & 3) << 2;
            float4 v = make_float4(0.f, 0.f, 0.f, 0.f);
            int gr = mBase + r;
            if (gr < NN) v = *reinterpret_cast<const float4*>(A + (size_t)gr * HID + kc + cg);
            As[cg + 0][r] = v.x; As[cg + 1][r] = v.y; As[cg + 2][r] = v.z; As[cg + 3][r] = v.w;
            // B tile: 16 ks x 128 ns = 512 float4
            int k = f >> 5, n4 = (f & 31) << 2;
            *reinterpret_cast<float4*>(&Bs[k][n4]) =
                *reinterpret_cast<const float4*>(B + (size_t)(kc + k) * HID + n4);
        }
        __syncthreads();
        #pragma unroll
        for (int kk = 0; kk < 16; kk++) {
            float ra[8], rb[8];
            #pragma unroll
            for (int i = 0; i < 8; i++) ra[i] = As[kk][tr * 8 + i];
            #pragma unroll
            for (int j = 0; j < 8; j++) rb[j] = Bs[kk][tc * 8 + j];
            #pragma unroll
            for (int i = 0; i < 8; i++)
                #pragma unroll
                for (int j = 0; j < 8; j++) acc[i][j] += ra[i] * rb[j];
        }
        __syncthreads();
    }
    #pragma unroll
    for (int i = 0; i < 8; i++) {
        int gr = mBase + tr * 8 + i;
        if (gr < NN) {
            float4 o0 = make_float4(acc[i][0], acc[i][1], acc[i][2], acc[i][3]);
            float4 o1 = make_float4(acc[i][4], acc[i][5], acc[i][6], acc[i][7]);
            *reinterpret_cast<float4*>(C + (size_t)gr * HID + tc * 8)     = o0;
            *reinterpret_cast<float4*>(C + (size_t)gr * HID + tc * 8 + 4) = o1;
        }
    }
}

// ---------------- per-node att_l / att_r dot products ----------------
__global__ void k_aux(int sel, const float* __restrict__ attl, const float* __restrict__ attr) {
    int gw = (blockIdx.x * blockDim.x + threadIdx.x) >> 5;
    if (gw >= NN) return;
    int lane = threadIdx.x & 31;
    const float* h = sel ? d_h2 : d_h1;
    float4 hv = reinterpret_cast<const float4*>(h + (size_t)gw * HID)[lane];
    float4 lv = reinterpret_cast<const float4*>(attl)[lane];
    float4 rv = reinterpret_cast<const float4*>(attr)[lane];
    float pl = hv.x * lv.x + hv.y * lv.y + hv.z * lv.z + hv.w * lv.w;
    float pr = hv.x * rv.x + hv.y * rv.y + hv.z * rv.z + hv.w * rv.w;
    #pragma unroll
    for (int off = 16; off; off >>= 1) {
        pl += __shfl_xor_sync(0xffffffffu, pl, off);
        pr += __shfl_xor_sync(0xffffffffu, pr, off);
    }
    if (lane == 0) { d_al[gw] = pl; d_ar[gw] = pr; }
}

// ---------------- fused SuperGAT attention layer (warp per dst node) ----------------
__global__ void k_attn(int selH, const float* __restrict__ bias, int selOut, int doRelu) {
    int gw = (blockIdx.x * blockDim.x + threadIdx.x) >> 5;
    if (gw >= NN) return;
    int lane = threadIdx.x & 31;
    const float* h = selH ? d_h2 : d_h1;
    float* out = selOut ? d_t2 : d_t1;

    float4 hd = reinterpret_cast<const float4*>(h + (size_t)gw * HID)[lane];
    float ard = d_ar[gw];
    int beg = d_rowptr[gw], end = d_rowptr[gw + 1];

    // pass 1: gated alpha + segment max
    float m = -3.4e38f;
    for (int i = beg; i < end; i++) {
        int s = d_src[i];
        float4 hs = reinterpret_cast<const float4*>(h + (size_t)s * HID)[lane];
        float p = hd.x * hs.x + hd.y * hs.y + hd.z * hs.z + hd.w * hs.w;
        #pragma unroll
        for (int off = 16; off; off >>= 1) p += __shfl_xor_sync(0xffffffffu, p, off);
        float a = d_al[s] + ard;
        a = a * (1.0f / (1.0f + __expf(-p)));   // MX gating
        if (lane == 0) d_scr[i] = a;
        m = fmaxf(m, a);
    }
    __syncwarp();

    // pass 2: exp, weighted aggregate, denom
    float4 acc = make_float4(0.f, 0.f, 0.f, 0.f);
    float ss = 0.f;
    for (int i = beg; i < end; i++) {
        int s = d_src[i];
        float ea = __expf(d_scr[i] - m);
        float4 hs = reinterpret_cast<const float4*>(h + (size_t)s * HID)[lane];
        acc.x += ea * hs.x; acc.y += ea * hs.y; acc.z += ea * hs.z; acc.w += ea * hs.w;
        ss += ea;
    }
    float inv = 1.0f / (ss + 1e-16f);
    float4 bv = reinterpret_cast<const float4*>(bias)[lane];
    float4 o = make_float4(acc.x * inv + bv.x, acc.y * inv + bv.y,
                           acc.z * inv + bv.z, acc.w * inv + bv.w);
    if (doRelu) {
        o.x = fmaxf(o.x, 0.f); o.y = fmaxf(o.y, 0.f);
        o.z = fmaxf(o.z, 0.f); o.w = fmaxf(o.w, 0.f);
    }
    reinterpret_cast<float4*>(out + (size_t)gw * HID)[lane] = o;
}

// ---------------- per-node classifier partials p = [h@Wc_top, h@Wc_bot] ----------------
__global__ void k_proj(const float* __restrict__ Wc) {
    int gw = (blockIdx.x * blockDim.x + threadIdx.x) >> 5;
    if (gw >= NN) return;
    int lane = threadIdx.x & 31;
    float4 hv = reinterpret_cast<const float4*>(d_t2 + (size_t)gw * HID)[lane];
    const float4* WcV = reinterpret_cast<const float4*>(Wc);  // row k -> 4 outs
    int k0 = lane * 4;
    float hj[4] = {hv.x, hv.y, hv.z, hv.w};
    float4 as = make_float4(0.f, 0.f, 0.f, 0.f);
    float4 ad = make_float4(0.f, 0.f, 0.f, 0.f);
    #pragma unroll
    for (int j = 0; j < 4; j++) {
        float4 w = WcV[k0 + j];
        as.x += hj[j] * w.x; as.y += hj[j] * w.y; as.z += hj[j] * w.z; as.w += hj[j] * w.w;
        float4 w2 = WcV[128 + k0 + j];
        ad.x += hj[j] * w2.x; ad.y += hj[j] * w2.y; ad.z += hj[j] * w2.z; ad.w += hj[j] * w2.w;
    }
    #pragma unroll
    for (int off = 16; off; off >>= 1) {
        as.x += __shfl_xor_sync(0xffffffffu, as.x, off);
        as.y += __shfl_xor_sync(0xffffffffu, as.y, off);
        as.z += __shfl_xor_sync(0xffffffffu, as.z, off);
        as.w += __shfl_xor_sync(0xffffffffu, as.w, off);
        ad.x += __shfl_xor_sync(0xffffffffu, ad.x, off);
        ad.y += __shfl_xor_sync(0xffffffffu, ad.y, off);
        ad.z += __shfl_xor_sync(0xffffffffu, ad.z, off);
        ad.w += __shfl_xor_sync(0xffffffffu, ad.w, off);
    }
    if (lane == 0) {
        float4* pv = reinterpret_cast<float4*>(d_p + (size_t)gw * 8);
        pv[0] = as; pv[1] = ad;
    }
}

// ---------------- per-edge output: out[e] = p_src[row] + p_dst[col] + bc ----------------
__global__ void k_edge(const int* __restrict__ ei, const float* __restrict__ bc,
                       float* __restrict__ out) {
    int e = blockIdx.x * blockDim.x + threadIdx.x;
    if (e >= EE) return;
    int r = ei[e], c = ei[EE + e];
    const float4* pv = reinterpret_cast<const float4*>(d_p);
    float4 a = pv[r * 2];
    float4 b = pv[c * 2 + 1];
    float4 bc4 = *reinterpret_cast<const float4*>(bc);
    float4 o = make_float4(a.x + b.x + bc4.x, a.y + b.y + bc4.y,
                           a.z + b.z + bc4.z, a.w + b.w + bc4.w);
    reinterpret_cast<float4*>(out)[e] = o;
}

// ---------------- launcher ----------------
extern "C" void kernel_launch(void* const* d_in, const int* in_sizes, int n_in,
                              void* d_out, int out_size) {
    const float* x   = (const float*)d_in[0];
    const int*   ei  = (const int*)  d_in[1];
    const float* W1  = (const float*)d_in[2];
    const float* al1 = (const float*)d_in[3];
    const float* ar1 = (const float*)d_in[4];
    const float* b1  = (const float*)d_in[5];
    const float* W2  = (const float*)d_in[6];
    const float* al2 = (const float*)d_in[7];
    const float* ar2 = (const float*)d_in[8];
    const float* b2  = (const float*)d_in[9];
    const float* Wc  = (const float*)d_in[10];
    const float* bc  = (const float*)d_in[11];
    float* out = (float*)d_out;

    // CSR build
    k_init<<<(NN + 255) / 256, 256>>>();
    k_hist<<<(EE + 255) / 256, 256>>>(ei);
    k_scan1<<<49, 1024>>>();
    k_scan2<<<1, 32>>>(49);
    k_scan3<<<49, 1024>>>();
    k_scatter<<<(ETOT + 255) / 256, 256>>>(ei);

    // layer 1
    k_gemm<<<(NN + 127) / 128, 256>>>(x, W1, 0, 0);
    k_aux<<<(NN + 7) / 8, 256>>>(0, al1, ar1);
    k_attn<<<(NN + 7) / 8, 256>>>(0, b1, 0, 1);

    // layer 2
    k_gemm<<<(NN + 127) / 128, 256>>>(nullptr, W2, 1, 1);
    k_aux<<<(NN + 7) / 8, 256>>>(1, al2, ar2);
    k_attn<<<(NN + 7) / 8, 256>>>(1, b2, 1, 0);

    // edge classifier
    k_proj<<<(NN + 7) / 8, 256>>>(Wc);
    k_edge<<<(EE + 255) / 256, 256>>>(ei, bc, out);
}

// round 2
// speedup vs baseline: 1.3601x; 1.3601x over previous
#include <cuda_runtime.h>

#define NN   50000
#define EE   800000
#define ETOT (EE + NN)
#define HID  128

// ---------------- device scratch (no allocations allowed) ----------------
__device__ float d_h1[NN * HID];   // x @ W1
__device__ float d_t1[NN * HID];   // relu(layer1 out)
__device__ float d_h2[NN * HID];   // t1 @ W2
__device__ float d_t2[NN * HID];   // layer2 out
__device__ float d_al[NN];
__device__ float d_ar[NN];
__device__ int   d_src[ETOT];      // CSR src list (sorted by dst)
__device__ int   d_rowptr[NN + 1];
__device__ int   d_deg[NN];
__device__ int   d_fill[NN];
__device__ int   d_bsums[64];
__device__ float d_p[NN * 8];      // per-node [p_src(4), p_dst(4)]

// ---------------- CSR build ----------------
__global__ void k_hist(const int* __restrict__ ei) {
    int e = blockIdx.x * blockDim.x + threadIdx.x;
    if (e < EE) atomicAdd(&d_deg[ei[EE + e]], 1);
}

__global__ void k_scan1() {
    __shared__ int sh[1024];
    int tid = threadIdx.x;
    int i = blockIdx.x * 1024 + tid;
    int v = (i < NN) ? (d_deg[i] + 1) : 0;     // +1 = self-loop
    sh[tid] = v;
    __syncthreads();
    #pragma unroll
    for (int off = 1; off < 1024; off <<= 1) {
        int t = (tid >= off) ? sh[tid - off] : 0;
        __syncthreads();
        sh[tid] += t;
        __syncthreads();
    }
    if (i < NN) d_rowptr[i] = sh[tid] - v;             // exclusive within block
    if (tid == 1023) d_bsums[blockIdx.x] = sh[1023];   // block total
}

// merged scan2+scan3: per-block offset computed by summing preceding block sums
__global__ void k_scan2b() {
    __shared__ int soff;
    if (threadIdx.x == 0) {
        int run = 0;
        for (int b = 0; b < (int)blockIdx.x; b++) run += d_bsums[b];
        soff = run;
    }
    __syncthreads();
    int i = blockIdx.x * 1024 + threadIdx.x;
    if (i < NN) { d_rowptr[i] += soff; d_fill[i] = 0; }
    if (i == 0) d_rowptr[NN] = ETOT;
}

__global__ void k_scatter(const int* __restrict__ ei) {
    int t = blockIdx.x * blockDim.x + threadIdx.x;
    if (t < EE) {
        int c = ei[EE + t];
        int pos = d_rowptr[c] + atomicAdd(&d_fill[c], 1);
        d_src[pos] = ei[t];
    } else if (t < ETOT) {
        int n = t - EE;
        int pos = d_rowptr[n] + atomicAdd(&d_fill[n], 1);
        d_src[pos] = n;
    }
}

// ---------------- GEMM: C[M,128] = A[M,128] @ B[128,128], fp32 ----------------
// block tile 128x128, thread tile 8x8, 256 threads.
// Fused epilogue: per-row dots with att_l / att_r -> d_al / d_ar.
__global__ void __launch_bounds__(256) k_gemm(const float* __restrict__ Aext,
                                              const float* __restrict__ B,
                                              const float* __restrict__ attl,
                                              const float* __restrict__ attr,
                                              int selA, int selC) {
    const float* A = selA ? d_t1 : Aext;
    float* C = selC ? d_h2 : d_h1;

    __shared__ float As[16][132];   // [k][m], padded
    __shared__ float Bs[16][128];   // [k][n]

    int tid = threadIdx.x;
    int tr = tid >> 4, tc = tid & 15;
    int mBase = blockIdx.x * 128;

    float acc[8][8];
    #pragma unroll
    for (int i = 0; i < 8; i++)
        #pragma unroll
        for (int j = 0; j < 8; j++) acc[i][j] = 0.f;

    for (int kc = 0; kc < 128; kc += 16) {
        #pragma unroll
        for (int l = 0; l < 2; l++) {
            int f = tid + l * 256;
            int r = f >> 2, cg = (f & 3) << 2;
            float4 v = make_float4(0.f, 0.f, 0.f, 0.f);
            int gr = mBase + r;
            if (gr < NN) v = *reinterpret_cast<const float4*>(A + (size_t)gr * HID + kc + cg);
            As[cg + 0][r] = v.x; As[cg + 1][r] = v.y; As[cg + 2][r] = v.z; As[cg + 3][r] = v.w;
            int k = f >> 5, n4 = (f & 31) << 2;
            *reinterpret_cast<float4*>(&Bs[k][n4]) =
                *reinterpret_cast<const float4*>(B + (size_t)(kc + k) * HID + n4);
        }
        __syncthreads();
        #pragma unroll
        for (int kk = 0; kk < 16; kk++) {
            float ra[8], rb[8];
            #pragma unroll
            for (int i = 0; i < 8; i++) ra[i] = As[kk][tr * 8 + i];
            #pragma unroll
            for (int j = 0; j < 8; j++) rb[j] = Bs[kk][tc * 8 + j];
            #pragma unroll
            for (int i = 0; i < 8; i++)
                #pragma unroll
                for (int j = 0; j < 8; j++) acc[i][j] += ra[i] * rb[j];
        }
        __syncthreads();
    }

    // epilogue: store C + fused att dots
    float alv[8], arv[8];
    #pragma unroll
    for (int j = 0; j < 8; j++) { alv[j] = attl[tc * 8 + j]; arv[j] = attr[tc * 8 + j]; }

    #pragma unroll
    for (int i = 0; i < 8; i++) {
        int gr = mBase + tr * 8 + i;
        float pl = 0.f, pr = 0.f;
        #pragma unroll
        for (int j = 0; j < 8; j++) { pl += acc[i][j] * alv[j]; pr += acc[i][j] * arv[j]; }
        #pragma unroll
        for (int off = 8; off; off >>= 1) {
            pl += __shfl_xor_sync(0xffffffffu, pl, off);
            pr += __shfl_xor_sync(0xffffffffu, pr, off);
        }
        if (gr < NN) {
            float4 o0 = make_float4(acc[i][0], acc[i][1], acc[i][2], acc[i][3]);
            float4 o1 = make_float4(acc[i][4], acc[i][5], acc[i][6], acc[i][7]);
            *reinterpret_cast<float4*>(C + (size_t)gr * HID + tc * 8)     = o0;
            *reinterpret_cast<float4*>(C + (size_t)gr * HID + tc * 8 + 4) = o1;
            if (tc == 0) { d_al[gr] = pl; d_ar[gr] = pr; }
        }
    }
}

// ---------------- fused SuperGAT attention, ONLINE softmax (warp per dst) ----------------
__global__ void k_attn(int selH, const float* __restrict__ bias, int selOut, int doRelu) {
    int gw = (blockIdx.x * blockDim.x + threadIdx.x) >> 5;
    if (gw >= NN) return;
    int lane = threadIdx.x & 31;
    const float* h = selH ? d_h2 : d_h1;
    float* out = selOut ? d_t2 : d_t1;

    float4 hd = reinterpret_cast<const float4*>(h + (size_t)gw * HID)[lane];
    float ard = d_ar[gw];
    int beg = d_rowptr[gw], end = d_rowptr[gw + 1];

    float m = -1e30f, ss = 0.f;
    float4 acc = make_float4(0.f, 0.f, 0.f, 0.f);

    int i = beg;
    for (; i + 1 < end; i += 2) {
        int s0 = d_src[i], s1 = d_src[i + 1];
        float al0 = d_al[s0], al1 = d_al[s1];
        float4 h0 = reinterpret_cast<const float4*>(h + (size_t)s0 * HID)[lane];
        float4 h1 = reinterpret_cast<const float4*>(h + (size_t)s1 * HID)[lane];
        float p0 = hd.x * h0.x + hd.y * h0.y + hd.z * h0.z + hd.w * h0.w;
        float p1 = hd.x * h1.x + hd.y * h1.y + hd.z * h1.z + hd.w * h1.w;
        #pragma unroll
        for (int off = 16; off; off >>= 1) {
            p0 += __shfl_xor_sync(0xffffffffu, p0, off);
            p1 += __shfl_xor_sync(0xffffffffu, p1, off);
        }
        float a0 = (al0 + ard) * (1.0f / (1.0f + __expf(-p0)));
        float a1 = (al1 + ard) * (1.0f / (1.0f + __expf(-p1)));
        float mn = fmaxf(m, fmaxf(a0, a1));
        float sc = __expf(m - mn);
        float e0 = __expf(a0 - mn);
        float e1 = __expf(a1 - mn);
        acc.x = acc.x * sc + e0 * h0.x + e1 * h1.x;
        acc.y = acc.y * sc + e0 * h0.y + e1 * h1.y;
        acc.z = acc.z * sc + e0 * h0.z + e1 * h1.z;
        acc.w = acc.w * sc + e0 * h0.w + e1 * h1.w;
        ss = ss * sc + e0 + e1;
        m = mn;
    }
    if (i < end) {
        int s0 = d_src[i];
        float al0 = d_al[s0];
        float4 h0 = reinterpret_cast<const float4*>(h + (size_t)s0 * HID)[lane];
        float p0 = hd.x * h0.x + hd.y * h0.y + hd.z * h0.z + hd.w * h0.w;
        #pragma unroll
        for (int off = 16; off; off >>= 1) p0 += __shfl_xor_sync(0xffffffffu, p0, off);
        float a0 = (al0 + ard) * (1.0f / (1.0f + __expf(-p0)));
        float mn = fmaxf(m, a0);
        float sc = __expf(m - mn);
        float e0 = __expf(a0 - mn);
        acc.x = acc.x * sc + e0 * h0.x;
        acc.y = acc.y * sc + e0 * h0.y;
        acc.z = acc.z * sc + e0 * h0.z;
        acc.w = acc.w * sc + e0 * h0.w;
        ss = ss * sc + e0;
    }

    float inv = 1.0f / (ss + 1e-16f);
    float4 bv = reinterpret_cast<const float4*>(bias)[lane];
    float4 o = make_float4(acc.x * inv + bv.x, acc.y * inv + bv.y,
                           acc.z * inv + bv.z, acc.w * inv + bv.w);
    if (doRelu) {
        o.x = fmaxf(o.x, 0.f); o.y = fmaxf(o.y, 0.f);
        o.z = fmaxf(o.z, 0.f); o.w = fmaxf(o.w, 0.f);
    }
    reinterpret_cast<float4*>(out + (size_t)gw * HID)[lane] = o;
}

// ---------------- per-node classifier partials p = [h@Wc_top, h@Wc_bot] ----------------
__global__ void k_proj(const float* __restrict__ Wc) {
    int gw = (blockIdx.x * blockDim.x + threadIdx.x) >> 5;
    if (gw >= NN) return;
    int lane = threadIdx.x & 31;
    float4 hv = reinterpret_cast<const float4*>(d_t2 + (size_t)gw * HID)[lane];
    const float4* WcV = reinterpret_cast<const float4*>(Wc);  // row k -> 4 outs
    int k0 = lane * 4;
    float hj[4] = {hv.x, hv.y, hv.z, hv.w};
    float4 as = make_float4(0.f, 0.f, 0.f, 0.f);
    float4 ad = make_float4(0.f, 0.f, 0.f, 0.f);
    #pragma unroll
    for (int j = 0; j < 4; j++) {
        float4 w = WcV[k0 + j];
        as.x += hj[j] * w.x; as.y += hj[j] * w.y; as.z += hj[j] * w.z; as.w += hj[j] * w.w;
        float4 w2 = WcV[128 + k0 + j];
        ad.x += hj[j] * w2.x; ad.y += hj[j] * w2.y; ad.z += hj[j] * w2.z; ad.w += hj[j] * w2.w;
    }
    #pragma unroll
    for (int off = 16; off; off >>= 1) {
        as.x += __shfl_xor_sync(0xffffffffu, as.x, off);
        as.y += __shfl_xor_sync(0xffffffffu, as.y, off);
        as.z += __shfl_xor_sync(0xffffffffu, as.z, off);
        as.w += __shfl_xor_sync(0xffffffffu, as.w, off);
        ad.x += __shfl_xor_sync(0xffffffffu, ad.x, off);
        ad.y += __shfl_xor_sync(0xffffffffu, ad.y, off);
        ad.z += __shfl_xor_sync(0xffffffffu, ad.z, off);
        ad.w += __shfl_xor_sync(0xffffffffu, ad.w, off);
    }
    if (lane == 0) {
        float4* pv = reinterpret_cast<float4*>(d_p + (size_t)gw * 8);
        pv[0] = as; pv[1] = ad;
    }
}

// ---------------- per-edge output: out[e] = p_src[row] + p_dst[col] + bc ----------------
__global__ void k_edge(const int* __restrict__ ei, const float* __restrict__ bc,
                       float* __restrict__ out) {
    int e = blockIdx.x * blockDim.x + threadIdx.x;
    if (e >= EE) return;
    int r = ei[e], c = ei[EE + e];
    const float4* pv = reinterpret_cast<const float4*>(d_p);
    float4 a = pv[r * 2];
    float4 b = pv[c * 2 + 1];
    float4 bc4 = *reinterpret_cast<const float4*>(bc);
    float4 o = make_float4(a.x + b.x + bc4.x, a.y + b.y + bc4.y,
                           a.z + b.z + bc4.z, a.w + b.w + bc4.w);
    reinterpret_cast<float4*>(out)[e] = o;
}

// ---------------- launcher ----------------
extern "C" void kernel_launch(void* const* d_in, const int* in_sizes, int n_in,
                              void* d_out, int out_size) {
    const float* x   = (const float*)d_in[0];
    const int*   ei  = (const int*)  d_in[1];
    const float* W1  = (const float*)d_in[2];
    const float* al1 = (const float*)d_in[3];
    const float* ar1 = (const float*)d_in[4];
    const float* b1  = (const float*)d_in[5];
    const float* W2  = (const float*)d_in[6];
    const float* al2 = (const float*)d_in[7];
    const float* ar2 = (const float*)d_in[8];
    const float* b2  = (const float*)d_in[9];
    const float* Wc  = (const float*)d_in[10];
    const float* bc  = (const float*)d_in[11];
    float* out = (float*)d_out;

    // zero degree histogram via graph memset node (not a kernel launch)
    void* degPtr = nullptr;
    cudaGetSymbolAddress(&degPtr, d_deg);
    cudaMemsetAsync(degPtr, 0, NN * sizeof(int));

    // launch order chosen so ncu (-s 5 -c 1) captures launch #6 = k_attn layer 1
    k_gemm<<<(NN + 127) / 128, 256>>>(x, W1, al1, ar1, 0, 0);          // 1
    k_hist<<<(EE + 255) / 256, 256>>>(ei);                             // 2
    k_scan1<<<49, 1024>>>();                                           // 3
    k_scan2b<<<49, 1024>>>();                                          // 4
    k_scatter<<<(ETOT + 255) / 256, 256>>>(ei);                        // 5
    k_attn<<<(NN * 32 + 255) / 256, 256>>>(0, b1, 0, 1);               // 6  <- profiled
    k_gemm<<<(NN + 127) / 128, 256>>>(nullptr, W2, al2, ar2, 1, 1);    // 7
    k_attn<<<(NN * 32 + 255) / 256, 256>>>(1, b2, 1, 0);               // 8
    k_proj<<<(NN + 7) / 8, 256>>>(Wc);                                 // 9
    k_edge<<<(EE + 255) / 256, 256>>>(ei, bc, out);                    // 10
}

// round 3
// speedup vs baseline: 1.4802x; 1.0883x over previous
#include <cuda_runtime.h>

#define NN   50000
#define EE   800000
#define ETOT (EE + NN)
#define HID  128

// ---------------- device scratch (no allocations allowed) ----------------
__device__ float d_h1[NN * HID];   // x @ W1
__device__ float d_t1[NN * HID];   // relu(layer1 out)
__device__ float d_h2[NN * HID];   // t1 @ W2
__device__ float d_al[NN];
__device__ float d_ar[NN];
__device__ int   d_src[ETOT];      // CSR src list (sorted by dst)
__device__ int   d_rowptr[NN + 1];
__device__ int   d_deg[NN];
__device__ int   d_fill[NN];
__device__ int   d_bsums[64];
__device__ float d_p[NN * 8];      // per-node [p_src(4), p_dst(4)]

// ---------------- CSR build ----------------
__global__ void k_hist(const int* __restrict__ ei) {
    int e = blockIdx.x * blockDim.x + threadIdx.x;
    if (e < EE) atomicAdd(&d_deg[ei[EE + e]], 1);
}

__global__ void k_scan1() {
    __shared__ int sh[1024];
    int tid = threadIdx.x;
    int i = blockIdx.x * 1024 + tid;
    int v = (i < NN) ? (d_deg[i] + 1) : 0;     // +1 = self-loop
    sh[tid] = v;
    __syncthreads();
    #pragma unroll
    for (int off = 1; off < 1024; off <<= 1) {
        int t = (tid >= off) ? sh[tid - off] : 0;
        __syncthreads();
        sh[tid] += t;
        __syncthreads();
    }
    if (i < NN) d_rowptr[i] = sh[tid] - v;             // exclusive within block
    if (tid == 1023) d_bsums[blockIdx.x] = sh[1023];   // block total
}

// merged scan2+scan3: per-block offset computed by summing preceding block sums
__global__ void k_scan2b() {
    __shared__ int soff;
    if (threadIdx.x == 0) {
        int run = 0;
        for (int b = 0; b < (int)blockIdx.x; b++) run += d_bsums[b];
        soff = run;
    }
    __syncthreads();
    int i = blockIdx.x * 1024 + threadIdx.x;
    if (i < NN) { d_rowptr[i] += soff; d_fill[i] = 0; }
    if (i == 0) d_rowptr[NN] = ETOT;
}

__global__ void k_scatter(const int* __restrict__ ei) {
    int t = blockIdx.x * blockDim.x + threadIdx.x;
    if (t < EE) {
        int c = ei[EE + t];
        int pos = d_rowptr[c] + atomicAdd(&d_fill[c], 1);
        d_src[pos] = ei[t];
    } else if (t < ETOT) {
        int n = t - EE;
        int pos = d_rowptr[n] + atomicAdd(&d_fill[n], 1);
        d_src[pos] = n;
    }
}

// ---------------- GEMM: C[M,128] = A[M,128] @ B[128,128], fp32 ----------------
// block tile 128x128, thread tile 8x8, 256 threads.
// Fused epilogue: per-row dots with att_l / att_r -> d_al / d_ar.
__global__ void __launch_bounds__(256) k_gemm(const float* __restrict__ Aext,
                                              const float* __restrict__ B,
                                              const float* __restrict__ attl,
                                              const float* __restrict__ attr,
                                              int selA, int selC) {
    const float* A = selA ? d_t1 : Aext;
    float* C = selC ? d_h2 : d_h1;

    __shared__ float As[16][132];   // [k][m], padded
    __shared__ float Bs[16][128];   // [k][n]

    int tid = threadIdx.x;
    int tr = tid >> 4, tc = tid & 15;
    int mBase = blockIdx.x * 128;

    float acc[8][8];
    #pragma unroll
    for (int i = 0; i < 8; i++)
        #pragma unroll
        for (int j = 0; j < 8; j++) acc[i][j] = 0.f;

    for (int kc = 0; kc < 128; kc += 16) {
        #pragma unroll
        for (int l = 0; l < 2; l++) {
            int f = tid + l * 256;
            int r = f >> 2, cg = (f & 3) << 2;
            float4 v = make_float4(0.f, 0.f, 0.f, 0.f);
            int gr = mBase + r;
            if (gr < NN) v = *reinterpret_cast<const float4*>(A + (size_t)gr * HID + kc + cg);
            As[cg + 0][r] = v.x; As[cg + 1][r] = v.y; As[cg + 2][r] = v.z; As[cg + 3][r] = v.w;
            int k = f >> 5, n4 = (f & 31) << 2;
            *reinterpret_cast<float4*>(&Bs[k][n4]) =
                *reinterpret_cast<const float4*>(B + (size_t)(kc + k) * HID + n4);
        }
        __syncthreads();
        #pragma unroll
        for (int kk = 0; kk < 16; kk++) {
            float ra[8], rb[8];
            #pragma unroll
            for (int i = 0; i < 8; i++) ra[i] = As[kk][tr * 8 + i];
            #pragma unroll
            for (int j = 0; j < 8; j++) rb[j] = Bs[kk][tc * 8 + j];
            #pragma unroll
            for (int i = 0; i < 8; i++)
                #pragma unroll
                for (int j = 0; j < 8; j++) acc[i][j] += ra[i] * rb[j];
        }
        __syncthreads();
    }

    // epilogue: store C + fused att dots
    float alv[8], arv[8];
    #pragma unroll
    for (int j = 0; j < 8; j++) { alv[j] = attl[tc * 8 + j]; arv[j] = attr[tc * 8 + j]; }

    #pragma unroll
    for (int i = 0; i < 8; i++) {
        int gr = mBase + tr * 8 + i;
        float pl = 0.f, pr = 0.f;
        #pragma unroll
        for (int j = 0; j < 8; j++) { pl += acc[i][j] * alv[j]; pr += acc[i][j] * arv[j]; }
        #pragma unroll
        for (int off = 8; off; off >>= 1) {
            pl += __shfl_xor_sync(0xffffffffu, pl, off);
            pr += __shfl_xor_sync(0xffffffffu, pr, off);
        }
        if (gr < NN) {
            float4 o0 = make_float4(acc[i][0], acc[i][1], acc[i][2], acc[i][3]);
            float4 o1 = make_float4(acc[i][4], acc[i][5], acc[i][6], acc[i][7]);
            *reinterpret_cast<float4*>(C + (size_t)gr * HID + tc * 8)     = o0;
            *reinterpret_cast<float4*>(C + (size_t)gr * HID + tc * 8 + 4) = o1;
            if (tc == 0) { d_al[gr] = pl; d_ar[gr] = pr; }
        }
    }
}

// ---------------- fused SuperGAT attention, ONLINE softmax (warp per dst) ----------------
// doProj: instead of storing the output row, compute classifier partials into d_p.
__global__ void k_attn(int selH, const float* __restrict__ bias, int doRelu,
                       int doProj, const float* __restrict__ Wc) {
    int gw = (blockIdx.x * blockDim.x + threadIdx.x) >> 5;
    if (gw >= NN) return;
    int lane = threadIdx.x & 31;
    const float* h = selH ? d_h2 : d_h1;

    float4 hd = reinterpret_cast<const float4*>(h + (size_t)gw * HID)[lane];
    float ard = d_ar[gw];
    int beg = d_rowptr[gw], end = d_rowptr[gw + 1];

    float m = -1e30f, ss = 0.f;
    float4 acc = make_float4(0.f, 0.f, 0.f, 0.f);

    int i = beg;
    // 4-wide unroll: 4 concurrent gathers + 4 interleaved shuffle trees
    for (; i + 3 < end; i += 4) {
        int s[4]; float alv[4]; float4 hs[4]; float p[4];
        #pragma unroll
        for (int j = 0; j < 4; j++) s[j] = d_src[i + j];
        #pragma unroll
        for (int j = 0; j < 4; j++) {
            alv[j] = d_al[s[j]];
            hs[j] = reinterpret_cast<const float4*>(h + (size_t)s[j] * HID)[lane];
        }
        #pragma unroll
        for (int j = 0; j < 4; j++)
            p[j] = hd.x * hs[j].x + hd.y * hs[j].y + hd.z * hs[j].z + hd.w * hs[j].w;
        #pragma unroll
        for (int off = 16; off; off >>= 1) {
            #pragma unroll
            for (int j = 0; j < 4; j++)
                p[j] += __shfl_xor_sync(0xffffffffu, p[j], off);
        }
        float a[4], mn = m;
        #pragma unroll
        for (int j = 0; j < 4; j++) {
            a[j] = (alv[j] + ard) * (1.0f / (1.0f + __expf(-p[j])));
            mn = fmaxf(mn, a[j]);
        }
        float sc = __expf(m - mn);
        float e[4];
        #pragma unroll
        for (int j = 0; j < 4; j++) e[j] = __expf(a[j] - mn);
        acc.x = acc.x * sc + e[0] * hs[0].x + e[1] * hs[1].x + e[2] * hs[2].x + e[3] * hs[3].x;
        acc.y = acc.y * sc + e[0] * hs[0].y + e[1] * hs[1].y + e[2] * hs[2].y + e[3] * hs[3].y;
        acc.z = acc.z * sc + e[0] * hs[0].z + e[1] * hs[1].z + e[2] * hs[2].z + e[3] * hs[3].z;
        acc.w = acc.w * sc + e[0] * hs[0].w + e[1] * hs[1].w + e[2] * hs[2].w + e[3] * hs[3].w;
        ss = ss * sc + e[0] + e[1] + e[2] + e[3];
        m = mn;
    }
    for (; i < end; i++) {
        int s0 = d_src[i];
        float al0 = d_al[s0];
        float4 h0 = reinterpret_cast<const float4*>(h + (size_t)s0 * HID)[lane];
        float p0 = hd.x * h0.x + hd.y * h0.y + hd.z * h0.z + hd.w * h0.w;
        #pragma unroll
        for (int off = 16; off; off >>= 1) p0 += __shfl_xor_sync(0xffffffffu, p0, off);
        float a0 = (al0 + ard) * (1.0f / (1.0f + __expf(-p0)));
        float mn = fmaxf(m, a0);
        float sc = __expf(m - mn);
        float e0 = __expf(a0 - mn);
        acc.x = acc.x * sc + e0 * h0.x;
        acc.y = acc.y * sc + e0 * h0.y;
        acc.z = acc.z * sc + e0 * h0.z;
        acc.w = acc.w * sc + e0 * h0.w;
        ss = ss * sc + e0;
        m = mn;
    }

    float inv = 1.0f / (ss + 1e-16f);
    float4 bv = reinterpret_cast<const float4*>(bias)[lane];
    float4 o = make_float4(acc.x * inv + bv.x, acc.y * inv + bv.y,
                           acc.z * inv + bv.z, acc.w * inv + bv.w);
    if (doRelu) {
        o.x = fmaxf(o.x, 0.f); o.y = fmaxf(o.y, 0.f);
        o.z = fmaxf(o.z, 0.f); o.w = fmaxf(o.w, 0.f);
    }

    if (!doProj) {
        reinterpret_cast<float4*>(d_t1 + (size_t)gw * HID)[lane] = o;
        return;
    }

    // fused classifier partials: as = o_row @ Wc[0:128], ad = o_row @ Wc[128:256]
    const float4* WcV = reinterpret_cast<const float4*>(Wc);  // row k -> float4
    int k0 = lane * 4;
    float hj[4] = {o.x, o.y, o.z, o.w};
    float4 as = make_float4(0.f, 0.f, 0.f, 0.f);
    float4 ad = make_float4(0.f, 0.f, 0.f, 0.f);
    #pragma unroll
    for (int j = 0; j < 4; j++) {
        float4 w = WcV[k0 + j];
        as.x += hj[j] * w.x; as.y += hj[j] * w.y; as.z += hj[j] * w.z; as.w += hj[j] * w.w;
        float4 w2 = WcV[128 + k0 + j];
        ad.x += hj[j] * w2.x; ad.y += hj[j] * w2.y; ad.z += hj[j] * w2.z; ad.w += hj[j] * w2.w;
    }
    #pragma unroll
    for (int off = 16; off; off >>= 1) {
        as.x += __shfl_xor_sync(0xffffffffu, as.x, off);
        as.y += __shfl_xor_sync(0xffffffffu, as.y, off);
        as.z += __shfl_xor_sync(0xffffffffu, as.z, off);
        as.w += __shfl_xor_sync(0xffffffffu, as.w, off);
        ad.x += __shfl_xor_sync(0xffffffffu, ad.x, off);
        ad.y += __shfl_xor_sync(0xffffffffu, ad.y, off);
        ad.z += __shfl_xor_sync(0xffffffffu, ad.z, off);
        ad.w += __shfl_xor_sync(0xffffffffu, ad.w, off);
    }
    if (lane == 0) {
        float4* pv = reinterpret_cast<float4*>(d_p + (size_t)gw * 8);
        pv[0] = as; pv[1] = ad;
    }
}

// ---------------- per-edge output: out[e] = p_src[row] + p_dst[col] + bc ----------------
__global__ void k_edge(const int* __restrict__ ei, const float* __restrict__ bc,
                       float* __restrict__ out) {
    int e = blockIdx.x * blockDim.x + threadIdx.x;
    if (e >= EE) return;
    int r = ei[e], c = ei[EE + e];
    const float4* pv = reinterpret_cast<const float4*>(d_p);
    float4 a = pv[r * 2];
    float4 b = pv[c * 2 + 1];
    float4 bc4 = *reinterpret_cast<const float4*>(bc);
    float4 o = make_float4(a.x + b.x + bc4.x, a.y + b.y + bc4.y,
                           a.z + b.z + bc4.z, a.w + b.w + bc4.w);
    reinterpret_cast<float4*>(out)[e] = o;
}

// ---------------- launcher ----------------
extern "C" void kernel_launch(void* const* d_in, const int* in_sizes, int n_in,
                              void* d_out, int out_size) {
    const float* x   = (const float*)d_in[0];
    const int*   ei  = (const int*)  d_in[1];
    const float* W1  = (const float*)d_in[2];
    const float* al1 = (const float*)d_in[3];
    const float* ar1 = (const float*)d_in[4];
    const float* b1  = (const float*)d_in[5];
    const float* W2  = (const float*)d_in[6];
    const float* al2 = (const float*)d_in[7];
    const float* ar2 = (const float*)d_in[8];
    const float* b2  = (const float*)d_in[9];
    const float* Wc  = (const float*)d_in[10];
    const float* bc  = (const float*)d_in[11];
    float* out = (float*)d_out;

    // side stream + fork/join events (created once; no device memory involved)
    static cudaStream_t s2 = nullptr;
    static cudaEvent_t evFork = nullptr, evJoin = nullptr;
    if (!s2) {
        cudaStreamCreateWithFlags(&s2, cudaStreamNonBlocking);
        cudaEventCreateWithFlags(&evFork, cudaEventDisableTiming);
        cudaEventCreateWithFlags(&evJoin, cudaEventDisableTiming);
    }

    // zero degree histogram via graph memset node (not a kernel launch)
    void* degPtr = nullptr;
    cudaGetSymbolAddress(&degPtr, d_deg);
    cudaMemsetAsync(degPtr, 0, NN * sizeof(int));

    // fork: CSR build chain on s2, concurrent with GEMM-1 on the main stream
    cudaEventRecord(evFork, 0);
    cudaStreamWaitEvent(s2, evFork, 0);

    k_hist<<<(EE + 255) / 256, 256, 0, s2>>>(ei);                        // kernel #1
    k_scan1<<<49, 1024, 0, s2>>>();                                      // kernel #2
    k_scan2b<<<49, 1024, 0, s2>>>();                                     // kernel #3
    k_gemm<<<(NN + 127) / 128, 256>>>(x, W1, al1, ar1, 0, 0);            // kernel #4 <- profiled
    k_scatter<<<(ETOT + 255) / 256, 256, 0, s2>>>(ei);                   // kernel #5

    // join: attention needs both GEMM-1 (stream 0) and CSR (s2)
    cudaEventRecord(evJoin, s2);
    cudaStreamWaitEvent(0, evJoin, 0);

    k_attn<<<(NN * 32 + 255) / 256, 256>>>(0, b1, 1, 0, nullptr);        // layer 1
    k_gemm<<<(NN + 127) / 128, 256>>>(nullptr, W2, al2, ar2, 1, 1);
    k_attn<<<(NN * 32 + 255) / 256, 256>>>(1, b2, 0, 1, Wc);             // layer 2 + fused proj
    k_edge<<<(EE + 255) / 256, 256>>>(ei, bc, out);
}

// round 4
// speedup vs baseline: 1.5722x; 1.0621x over previous
#include <cuda_runtime.h>

#define NN   50000
#define EE   800000
#define ETOT (EE + NN)
#define HID  128

// ---------------- device scratch (no allocations allowed) ----------------
__device__ float d_h1[NN * HID];   // x @ W1
__device__ float d_t1[NN * HID];   // relu(layer1 out)
__device__ float d_h2[NN * HID];   // t1 @ W2
__device__ float d_al[NN];
__device__ float d_ar[NN];
__device__ int   d_src[ETOT];      // CSR src list (sorted by dst)
__device__ int   d_rowptr[NN + 1];
__device__ int   d_deg[NN];
__device__ int   d_fill[NN];
__device__ int   d_bsums[64];
__device__ float d_p[NN * 8];      // per-node [p_src(4), p_dst(4)]

// ---------------- packed f32x2 helpers (sm_100+ FFMA2 path) ----------------
__device__ __forceinline__ unsigned long long pack2(float lo, float hi) {
    unsigned long long r;
    asm("mov.b64 %0,{%1,%2};" : "=l"(r) : "f"(lo), "f"(hi));
    return r;
}
__device__ __forceinline__ unsigned long long fma2(unsigned long long a,
                                                   unsigned long long b,
                                                   unsigned long long c) {
    unsigned long long d;
    asm("fma.rn.f32x2 %0,%1,%2,%3;" : "=l"(d) : "l"(a), "l"(b), "l"(c));
    return d;
}
__device__ __forceinline__ void unpack2(unsigned long long v, float& lo, float& hi) {
    asm("mov.b64 {%0,%1},%2;" : "=f"(lo), "=f"(hi) : "l"(v));
}

// ---------------- CSR build ----------------
__global__ void k_hist(const int* __restrict__ ei) {
    int e = blockIdx.x * blockDim.x + threadIdx.x;
    if (e < EE) atomicAdd(&d_deg[ei[EE + e]], 1);
}

__global__ void k_scan1() {
    __shared__ int sh[1024];
    int tid = threadIdx.x;
    int i = blockIdx.x * 1024 + tid;
    int v = (i < NN) ? (d_deg[i] + 1) : 0;     // +1 = self-loop
    sh[tid] = v;
    __syncthreads();
    #pragma unroll
    for (int off = 1; off < 1024; off <<= 1) {
        int t = (tid >= off) ? sh[tid - off] : 0;
        __syncthreads();
        sh[tid] += t;
        __syncthreads();
    }
    if (i < NN) d_rowptr[i] = sh[tid] - v;             // exclusive within block
    if (tid == 1023) d_bsums[blockIdx.x] = sh[1023];   // block total
}

__global__ void k_scan2b() {
    __shared__ int soff;
    if (threadIdx.x == 0) {
        int run = 0;
        for (int b = 0; b < (int)blockIdx.x; b++) run += d_bsums[b];
        soff = run;
    }
    __syncthreads();
    int i = blockIdx.x * 1024 + threadIdx.x;
    if (i < NN) { d_rowptr[i] += soff; d_fill[i] = 0; }
    if (i == 0) d_rowptr[NN] = ETOT;
}

__global__ void k_scatter(const int* __restrict__ ei) {
    int t = blockIdx.x * blockDim.x + threadIdx.x;
    if (t < EE) {
        int c = ei[EE + t];
        int pos = d_rowptr[c] + atomicAdd(&d_fill[c], 1);
        d_src[pos] = ei[t];
    } else if (t < ETOT) {
        int n = t - EE;
        int pos = d_rowptr[n] + atomicAdd(&d_fill[n], 1);
        d_src[pos] = n;
    }
}

// ---------------- GEMM: C[M,128] = A[M,128] @ B[128,128], fp32 via FFMA2 ----------------
// block tile 128x128, thread tile 8x8 (cols tc*4..+3 and 64+tc*4..+3), 256 threads.
// Accumulators held as packed f32x2 pairs; fused att_l/att_r epilogue.
__global__ void __launch_bounds__(256) k_gemm(const float* __restrict__ Aext,
                                              const float* __restrict__ B,
                                              const float* __restrict__ attl,
                                              const float* __restrict__ attr,
                                              int selA, int selC) {
    const float* A = selA ? d_t1 : Aext;
    float* C = selC ? d_h2 : d_h1;

    __shared__ float As[16][132];   // [k][m], padded
    __shared__ float Bs[16][128];   // [k][n]

    int tid = threadIdx.x;
    int tr = tid >> 4, tc = tid & 15;
    int mBase = blockIdx.x * 128;
    int c0 = tc * 4;        // column group 0
    int c1 = 64 + tc * 4;   // column group 1

    // acc[i][p]: p=0,1 -> cols c0..c0+3 ; p=2,3 -> cols c1..c1+3 (packed pairs)
    unsigned long long acc[8][4];
    unsigned long long z = pack2(0.f, 0.f);
    #pragma unroll
    for (int i = 0; i < 8; i++)
        #pragma unroll
        for (int p = 0; p < 4; p++) acc[i][p] = z;

    for (int kc = 0; kc < 128; kc += 16) {
        #pragma unroll
        for (int l = 0; l < 2; l++) {
            int f = tid + l * 256;
            int r = f >> 2, cg = (f & 3) << 2;
            float4 v = make_float4(0.f, 0.f, 0.f, 0.f);
            int gr = mBase + r;
            if (gr < NN) v = *reinterpret_cast<const float4*>(A + (size_t)gr * HID + kc + cg);
            As[cg + 0][r] = v.x; As[cg + 1][r] = v.y; As[cg + 2][r] = v.z; As[cg + 3][r] = v.w;
            int k = f >> 5, n4 = (f & 31) << 2;
            *reinterpret_cast<float4*>(&Bs[k][n4]) =
                *reinterpret_cast<const float4*>(B + (size_t)(kc + k) * HID + n4);
        }
        __syncthreads();
        #pragma unroll
        for (int kk = 0; kk < 16; kk++) {
            float4 a0 = *reinterpret_cast<const float4*>(&As[kk][tr * 8]);
            float4 a1 = *reinterpret_cast<const float4*>(&As[kk][tr * 8 + 4]);
            float4 b0 = *reinterpret_cast<const float4*>(&Bs[kk][c0]);
            float4 b1 = *reinterpret_cast<const float4*>(&Bs[kk][c1]);
            unsigned long long pb[4];
            pb[0] = pack2(b0.x, b0.y); pb[1] = pack2(b0.z, b0.w);
            pb[2] = pack2(b1.x, b1.y); pb[3] = pack2(b1.z, b1.w);
            float av[8] = {a0.x, a0.y, a0.z, a0.w, a1.x, a1.y, a1.z, a1.w};
            #pragma unroll
            for (int i = 0; i < 8; i++) {
                unsigned long long ad = pack2(av[i], av[i]);
                #pragma unroll
                for (int p = 0; p < 4; p++) acc[i][p] = fma2(ad, pb[p], acc[i][p]);
            }
        }
        __syncthreads();
    }

    // epilogue: unpack, store C, fused att dots
    float alv[8], arv[8];
    #pragma unroll
    for (int j = 0; j < 4; j++) {
        alv[j]     = attl[c0 + j]; arv[j]     = attr[c0 + j];
        alv[4 + j] = attl[c1 + j]; arv[4 + j] = attr[c1 + j];
    }

    #pragma unroll
    for (int i = 0; i < 8; i++) {
        int gr = mBase + tr * 8 + i;
        float cv[8];
        unpack2(acc[i][0], cv[0], cv[1]); unpack2(acc[i][1], cv[2], cv[3]);
        unpack2(acc[i][2], cv[4], cv[5]); unpack2(acc[i][3], cv[6], cv[7]);
        float pl = 0.f, pr = 0.f;
        #pragma unroll
        for (int j = 0; j < 8; j++) { pl += cv[j] * alv[j]; pr += cv[j] * arv[j]; }
        #pragma unroll
        for (int off = 8; off; off >>= 1) {
            pl += __shfl_xor_sync(0xffffffffu, pl, off);
            pr += __shfl_xor_sync(0xffffffffu, pr, off);
        }
        if (gr < NN) {
            float4 o0 = make_float4(cv[0], cv[1], cv[2], cv[3]);
            float4 o1 = make_float4(cv[4], cv[5], cv[6], cv[7]);
            *reinterpret_cast<float4*>(C + (size_t)gr * HID + c0) = o0;
            *reinterpret_cast<float4*>(C + (size_t)gr * HID + c1) = o1;
            if (tc == 0) { d_al[gr] = pl; d_ar[gr] = pr; }
        }
    }
}

// ---------------- fused SuperGAT attention, ONLINE softmax (warp per dst) ----------------
__global__ void k_attn(int selH, const float* __restrict__ bias, int doRelu,
                       int doProj, const float* __restrict__ Wc) {
    int gw = (blockIdx.x * blockDim.x + threadIdx.x) >> 5;
    if (gw >= NN) return;
    int lane = threadIdx.x & 31;
    const float* h = selH ? d_h2 : d_h1;

    float4 hd = reinterpret_cast<const float4*>(h + (size_t)gw * HID)[lane];
    float ard = d_ar[gw];
    int beg = d_rowptr[gw], end = d_rowptr[gw + 1];

    float m = -1e30f, ss = 0.f;
    float4 acc = make_float4(0.f, 0.f, 0.f, 0.f);

    int i = beg;
    for (; i + 3 < end; i += 4) {
        int s[4]; float alv[4]; float4 hs[4]; float p[4];
        #pragma unroll
        for (int j = 0; j < 4; j++) s[j] = d_src[i + j];
        #pragma unroll
        for (int j = 0; j < 4; j++) {
            alv[j] = d_al[s[j]];
            hs[j] = reinterpret_cast<const float4*>(h + (size_t)s[j] * HID)[lane];
        }
        #pragma unroll
        for (int j = 0; j < 4; j++)
            p[j] = hd.x * hs[j].x + hd.y * hs[j].y + hd.z * hs[j].z + hd.w * hs[j].w;
        #pragma unroll
        for (int off = 16; off; off >>= 1) {
            #pragma unroll
            for (int j = 0; j < 4; j++)
                p[j] += __shfl_xor_sync(0xffffffffu, p[j], off);
        }
        float a[4], mn = m;
        #pragma unroll
        for (int j = 0; j < 4; j++) {
            a[j] = (alv[j] + ard) * (1.0f / (1.0f + __expf(-p[j])));
            mn = fmaxf(mn, a[j]);
        }
        float sc = __expf(m - mn);
        float e[4];
        #pragma unroll
        for (int j = 0; j < 4; j++) e[j] = __expf(a[j] - mn);
        acc.x = acc.x * sc + e[0] * hs[0].x + e[1] * hs[1].x + e[2] * hs[2].x + e[3] * hs[3].x;
        acc.y = acc.y * sc + e[0] * hs[0].y + e[1] * hs[1].y + e[2] * hs[2].y + e[3] * hs[3].y;
        acc.z = acc.z * sc + e[0] * hs[0].z + e[1] * hs[1].z + e[2] * hs[2].z + e[3] * hs[3].z;
        acc.w = acc.w * sc + e[0] * hs[0].w + e[1] * hs[1].w + e[2] * hs[2].w + e[3] * hs[3].w;
        ss = ss * sc + e[0] + e[1] + e[2] + e[3];
        m = mn;
    }
    for (; i < end; i++) {
        int s0 = d_src[i];
        float al0 = d_al[s0];
        float4 h0 = reinterpret_cast<const float4*>(h + (size_t)s0 * HID)[lane];
        float p0 = hd.x * h0.x + hd.y * h0.y + hd.z * h0.z + hd.w * h0.w;
        #pragma unroll
        for (int off = 16; off; off >>= 1) p0 += __shfl_xor_sync(0xffffffffu, p0, off);
        float a0 = (al0 + ard) * (1.0f / (1.0f + __expf(-p0)));
        float mn = fmaxf(m, a0);
        float sc = __expf(m - mn);
        float e0 = __expf(a0 - mn);
        acc.x = acc.x * sc + e0 * h0.x;
        acc.y = acc.y * sc + e0 * h0.y;
        acc.z = acc.z * sc + e0 * h0.z;
        acc.w = acc.w * sc + e0 * h0.w;
        ss = ss * sc + e0;
        m = mn;
    }

    float inv = 1.0f / (ss + 1e-16f);
    float4 bv = reinterpret_cast<const float4*>(bias)[lane];
    float4 o = make_float4(acc.x * inv + bv.x, acc.y * inv + bv.y,
                           acc.z * inv + bv.z, acc.w * inv + bv.w);
    if (doRelu) {
        o.x = fmaxf(o.x, 0.f); o.y = fmaxf(o.y, 0.f);
        o.z = fmaxf(o.z, 0.f); o.w = fmaxf(o.w, 0.f);
    }

    if (!doProj) {
        reinterpret_cast<float4*>(d_t1 + (size_t)gw * HID)[lane] = o;
        return;
    }

    // fused classifier partials: as = o_row @ Wc[0:128], ad = o_row @ Wc[128:256]
    const float4* WcV = reinterpret_cast<const float4*>(Wc);
    int k0 = lane * 4;
    float hj[4] = {o.x, o.y, o.z, o.w};
    float4 as = make_float4(0.f, 0.f, 0.f, 0.f);
    float4 ad = make_float4(0.f, 0.f, 0.f, 0.f);
    #pragma unroll
    for (int j = 0; j < 4; j++) {
        float4 w = WcV[k0 + j];
        as.x += hj[j] * w.x; as.y += hj[j] * w.y; as.z += hj[j] * w.z; as.w += hj[j] * w.w;
        float4 w2 = WcV[128 + k0 + j];
        ad.x += hj[j] * w2.x; ad.y += hj[j] * w2.y; ad.z += hj[j] * w2.z; ad.w += hj[j] * w2.w;
    }
    #pragma unroll
    for (int off = 16; off; off >>= 1) {
        as.x += __shfl_xor_sync(0xffffffffu, as.x, off);
        as.y += __shfl_xor_sync(0xffffffffu, as.y, off);
        as.z += __shfl_xor_sync(0xffffffffu, as.z, off);
        as.w += __shfl_xor_sync(0xffffffffu, as.w, off);
        ad.x += __shfl_xor_sync(0xffffffffu, ad.x, off);
        ad.y += __shfl_xor_sync(0xffffffffu, ad.y, off);
        ad.z += __shfl_xor_sync(0xffffffffu, ad.z, off);
        ad.w += __shfl_xor_sync(0xffffffffu, ad.w, off);
    }
    if (lane == 0) {
        float4* pv = reinterpret_cast<float4*>(d_p + (size_t)gw * 8);
        pv[0] = as; pv[1] = ad;
    }
}

// ---------------- per-edge output: out[e] = p_src[row] + p_dst[col] + bc ----------------
__global__ void k_edge(const int* __restrict__ ei, const float* __restrict__ bc,
                       float* __restrict__ out) {
    int e = blockIdx.x * blockDim.x + threadIdx.x;
    if (e >= EE) return;
    int r = ei[e], c = ei[EE + e];
    const float4* pv = reinterpret_cast<const float4*>(d_p);
    float4 a = pv[r * 2];
    float4 b = pv[c * 2 + 1];
    float4 bc4 = *reinterpret_cast<const float4*>(bc);
    float4 o = make_float4(a.x + b.x + bc4.x, a.y + b.y + bc4.y,
                           a.z + b.z + bc4.z, a.w + b.w + bc4.w);
    reinterpret_cast<float4*>(out)[e] = o;
}

// ---------------- launcher ----------------
extern "C" void kernel_launch(void* const* d_in, const int* in_sizes, int n_in,
                              void* d_out, int out_size) {
    const float* x   = (const float*)d_in[0];
    const int*   ei  = (const int*)  d_in[1];
    const float* W1  = (const float*)d_in[2];
    const float* al1 = (const float*)d_in[3];
    const float* ar1 = (const float*)d_in[4];
    const float* b1  = (const float*)d_in[5];
    const float* W2  = (const float*)d_in[6];
    const float* al2 = (const float*)d_in[7];
    const float* ar2 = (const float*)d_in[8];
    const float* b2  = (const float*)d_in[9];
    const float* Wc  = (const float*)d_in[10];
    const float* bc  = (const float*)d_in[11];
    float* out = (float*)d_out;

    static cudaStream_t s2 = nullptr;
    static cudaEvent_t evFork = nullptr, evJoin = nullptr;
    if (!s2) {
        cudaStreamCreateWithFlags(&s2, cudaStreamNonBlocking);
        cudaEventCreateWithFlags(&evFork, cudaEventDisableTiming);
        cudaEventCreateWithFlags(&evJoin, cudaEventDisableTiming);
    }

    void* degPtr = nullptr;
    cudaGetSymbolAddress(&degPtr, d_deg);
    cudaMemsetAsync(degPtr, 0, NN * sizeof(int));

    // fork: CSR build chain on s2, concurrent with GEMM-1 on the main stream
    cudaEventRecord(evFork, 0);
    cudaStreamWaitEvent(s2, evFork, 0);

    k_hist<<<(EE + 255) / 256, 256, 0, s2>>>(ei);                        // #1
    k_scan1<<<49, 1024, 0, s2>>>();                                      // #2
    k_scan2b<<<49, 1024, 0, s2>>>();                                     // #3
    k_gemm<<<(NN + 127) / 128, 256>>>(x, W1, al1, ar1, 0, 0);            // #4 <- profiled
    k_scatter<<<(ETOT + 255) / 256, 256, 0, s2>>>(ei);                   // #5

    cudaEventRecord(evJoin, s2);
    cudaStreamWaitEvent(0, evJoin, 0);

    k_attn<<<(NN * 32 + 255) / 256, 256>>>(0, b1, 1, 0, nullptr);        // layer 1
    k_gemm<<<(NN + 127) / 128, 256>>>(nullptr, W2, al2, ar2, 1, 1);
    k_attn<<<(NN * 32 + 255) / 256, 256>>>(1, b2, 0, 1, Wc);             // layer 2 + proj
    k_edge<<<(EE + 255) / 256, 256>>>(ei, bc, out);
}